// round 1
// baseline (speedup 1.0000x reference)
#include <cuda_runtime.h>
#include <math.h>

// ---------------------------------------------------------------------------
// Problem constants (fixed by the reference): B=4, S=2048, D=1024, H=16, dk=64
// ---------------------------------------------------------------------------
#define BB 4
#define SS 2048
#define DD 1024
#define HH 16
#define DK 64
#define MM (BB * SS)          // 8192 rows for all projections

// Scratch: Q,K,V in [B,H,S,dk] layout; ctx in [B,S,D] layout.
__device__ float g_Q[(size_t)BB * HH * SS * DK];
__device__ float g_K[(size_t)BB * HH * SS * DK];
__device__ float g_V[(size_t)BB * HH * SS * DK];
__device__ float g_C[(size_t)BB * SS * DD];

// ---------------------------------------------------------------------------
// GEMM: out = A[M,K] @ W[K,N] + bias[N]
// 128x128 block tile, 8x8 per-thread micro-tile, 256 threads.
// splitHeads=1 writes out in [B,H,S,dk] layout instead of [M,N].
// ---------------------------------------------------------------------------
#define TM 128
#define TN 128
#define TK 16

__global__ __launch_bounds__(256)
void gemm_bias_kernel(const float* __restrict__ A,
                      const float* __restrict__ W,
                      const float* __restrict__ bias,
                      float* __restrict__ out,
                      int M, int N, int K, int splitHeads)
{
    __shared__ float As[TK][TM + 4];   // padded to dodge store conflicts
    __shared__ float Bs[TK][TN];

    const int rowBase = blockIdx.y * TM;
    const int colBase = blockIdx.x * TN;
    const int tid = threadIdx.x;
    const int ty = tid >> 4;           // 0..15
    const int tx = tid & 15;           // 0..15

    float acc[8][8];
#pragma unroll
    for (int i = 0; i < 8; i++)
#pragma unroll
        for (int j = 0; j < 8; j++) acc[i][j] = 0.f;

    for (int k0 = 0; k0 < K; k0 += TK) {
        // Load A tile: 128 x 16
#pragma unroll
        for (int i = 0; i < 8; i++) {
            int idx = tid + i * 256;           // 0..2047
            int r = idx >> 4, c = idx & 15;
            As[c][r] = A[(size_t)(rowBase + r) * K + (k0 + c)];
        }
        // Load B tile: 16 x 128 (coalesced)
#pragma unroll
        for (int i = 0; i < 8; i++) {
            int idx = tid + i * 256;
            int r = idx >> 7, c = idx & 127;
            Bs[r][c] = W[(size_t)(k0 + r) * N + (colBase + c)];
        }
        __syncthreads();

#pragma unroll
        for (int kk = 0; kk < TK; kk++) {
            float4 a0 = *(const float4*)&As[kk][ty * 8];
            float4 a1 = *(const float4*)&As[kk][ty * 8 + 4];
            float4 b0 = *(const float4*)&Bs[kk][tx * 8];
            float4 b1 = *(const float4*)&Bs[kk][tx * 8 + 4];
            float a[8] = {a0.x, a0.y, a0.z, a0.w, a1.x, a1.y, a1.z, a1.w};
            float b[8] = {b0.x, b0.y, b0.z, b0.w, b1.x, b1.y, b1.z, b1.w};
#pragma unroll
            for (int i = 0; i < 8; i++)
#pragma unroll
                for (int j = 0; j < 8; j++)
                    acc[i][j] += a[i] * b[j];
        }
        __syncthreads();
    }

    // Epilogue
#pragma unroll
    for (int i = 0; i < 8; i++) {
        int m = rowBase + ty * 8 + i;
#pragma unroll
        for (int j = 0; j < 8; j++) {
            int n = colBase + tx * 8 + j;
            float v = acc[i][j] + bias[n];
            if (splitHeads) {
                int b  = m >> 11;         // m / 2048
                int s  = m & (SS - 1);
                int h  = n >> 6;          // n / 64
                int dd = n & (DK - 1);
                out[(((size_t)(b * HH + h)) * SS + s) * DK + dd] = v;
            } else {
                out[(size_t)m * N + n] = v;
            }
        }
    }
}

// ---------------------------------------------------------------------------
// Causal flash attention, fp32. One block = 128 query rows of one (b,h).
// Each thread owns one query row: q[64] and acc[64] in registers.
// Streams K/V tiles of 16 keys through shared memory with online softmax.
// ---------------------------------------------------------------------------
#define KT 16

__global__ __launch_bounds__(128)
void attn_kernel(const float* __restrict__ Q,
                 const float* __restrict__ K,
                 const float* __restrict__ V,
                 float* __restrict__ C)
{
    __shared__ float4 Ks[KT][DK / 4];
    __shared__ float4 Vs[KT][DK / 4];

    const int qt = blockIdx.x;   // 0..15 (query tile)
    const int h  = blockIdx.y;   // 0..15
    const int b  = blockIdx.z;   // 0..3
    const size_t bh = (size_t)(b * HH + h);
    const float* Qb = Q + bh * SS * DK;
    const float* Kb = K + bh * SS * DK;
    const float* Vb = V + bh * SS * DK;

    const int qi = qt * 128 + threadIdx.x;   // this thread's query row

    // Load q row, pre-scaled by 1/sqrt(dk) = 0.125
    float4 q[DK / 4];
    const float4* qp = (const float4*)(Qb + (size_t)qi * DK);
#pragma unroll
    for (int i = 0; i < DK / 4; i++) {
        float4 t = qp[i];
        t.x *= 0.125f; t.y *= 0.125f; t.z *= 0.125f; t.w *= 0.125f;
        q[i] = t;
    }

    float4 acc[DK / 4];
#pragma unroll
    for (int i = 0; i < DK / 4; i++) acc[i] = make_float4(0.f, 0.f, 0.f, 0.f);
    float m = -INFINITY, l = 0.f;

    const int kend = qt * 128 + 128;         // causal: keys beyond this tile all masked

    for (int j0 = 0; j0 < kend; j0 += KT) {
        // Load KT x 64 floats of K and V (= 256 float4 each, 128 threads -> 2 each)
        const float4* Ksrc = (const float4*)(Kb + (size_t)j0 * DK);
        const float4* Vsrc = (const float4*)(Vb + (size_t)j0 * DK);
#pragma unroll
        for (int i = 0; i < 2; i++) {
            int idx = threadIdx.x + i * 128;
            ((float4*)Ks)[idx] = Ksrc[idx];
            ((float4*)Vs)[idx] = Vsrc[idx];
        }
        __syncthreads();

        // Scores for this key tile
        float s[KT];
#pragma unroll
        for (int j = 0; j < KT; j++) {
            float4 sum = make_float4(0.f, 0.f, 0.f, 0.f);
#pragma unroll
            for (int d = 0; d < DK / 4; d++) {
                float4 kk = Ks[j][d];
                sum.x += q[d].x * kk.x; sum.y += q[d].y * kk.y;
                sum.z += q[d].z * kk.z; sum.w += q[d].w * kk.w;
            }
            float sv = (sum.x + sum.y) + (sum.z + sum.w);
            s[j] = ((j0 + j) <= qi) ? sv : -INFINITY;
        }

        // Online softmax update
        float mt = m;
#pragma unroll
        for (int j = 0; j < KT; j++) mt = fmaxf(mt, s[j]);
        float scale = __expf(m - mt);        // 0 when m=-inf, mt finite
        l *= scale;
#pragma unroll
        for (int i = 0; i < DK / 4; i++) {
            acc[i].x *= scale; acc[i].y *= scale;
            acc[i].z *= scale; acc[i].w *= scale;
        }
#pragma unroll
        for (int j = 0; j < KT; j++) {
            float p = __expf(s[j] - mt);     // 0 for masked keys
            l += p;
#pragma unroll
            for (int d = 0; d < DK / 4; d++) {
                float4 vv = Vs[j][d];
                acc[d].x += p * vv.x; acc[d].y += p * vv.y;
                acc[d].z += p * vv.z; acc[d].w += p * vv.w;
            }
        }
        m = mt;
        __syncthreads();
    }

    // Write ctx in [B,S,D] layout
    const float inv = 1.f / l;
    float* outp = C + ((size_t)b * SS + qi) * DD + h * DK;
#pragma unroll
    for (int i = 0; i < DK / 4; i++) {
        float4 o = acc[i];
        o.x *= inv; o.y *= inv; o.z *= inv; o.w *= inv;
        ((float4*)outp)[i] = o;
    }
}

// ---------------------------------------------------------------------------
// Launch
// ---------------------------------------------------------------------------
extern "C" void kernel_launch(void* const* d_in, const int* in_sizes, int n_in,
                              void* d_out, int out_size)
{
    const float* q  = (const float*)d_in[0];
    const float* k  = (const float*)d_in[1];
    const float* v  = (const float*)d_in[2];
    // d_in[3] is the causal mask -> hardcoded
    const float* Wq = (const float*)d_in[4];
    const float* bq = (const float*)d_in[5];
    const float* Wk = (const float*)d_in[6];
    const float* bk = (const float*)d_in[7];
    const float* Wv = (const float*)d_in[8];
    const float* bv = (const float*)d_in[9];
    const float* Wo = (const float*)d_in[10];
    const float* bo = (const float*)d_in[11];

    float *gQ, *gK, *gV, *gC;
    cudaGetSymbolAddress((void**)&gQ, g_Q);
    cudaGetSymbolAddress((void**)&gK, g_K);
    cudaGetSymbolAddress((void**)&gV, g_V);
    cudaGetSymbolAddress((void**)&gC, g_C);

    dim3 gemmGrid(DD / TN, MM / TM);   // (8, 64)

    gemm_bias_kernel<<<gemmGrid, 256>>>(q, Wq, bq, gQ, MM, DD, DD, 1);
    gemm_bias_kernel<<<gemmGrid, 256>>>(k, Wk, bk, gK, MM, DD, DD, 1);
    gemm_bias_kernel<<<gemmGrid, 256>>>(v, Wv, bv, gV, MM, DD, DD, 1);

    attn_kernel<<<dim3(SS / 128, HH, BB), 128>>>(gQ, gK, gV, gC);

    gemm_bias_kernel<<<gemmGrid, 256>>>(gC, Wo, bo, (float*)d_out, MM, DD, DD, 0);
}